// round 11
// baseline (speedup 1.0000x reference)
#include <cuda_runtime.h>

typedef unsigned long long ULL;

__device__ __forceinline__ ULL fma2(ULL a, ULL b, ULL c) {
    ULL d;
    asm("fma.rn.f32x2 %0, %1, %2, %3;" : "=l"(d) : "l"(a), "l"(b), "l"(c));
    return d;
}
__device__ __forceinline__ ULL dup2(float x) {
    ULL d;
    asm("mov.b64 %0, {%1, %1};" : "=l"(d) : "f"(x));
    return d;
}
__device__ __forceinline__ float2 unpk(ULL v) {
    float2 r;
    asm("mov.b64 {%0, %1}, %2;" : "=f"(r.x), "=f"(r.y) : "l"(v));
    return r;
}
// opaque +0.0 maker: min(x, 0) with x > 0; ptxas cannot fold it away.
__device__ __forceinline__ float zero_of(float x) {
    float z;
    asm("min.f32 %0, %1, 0f00000000;" : "=f"(z) : "f"(x));
    return z;
}

#define N_TOT 8192
#define TN 8          // n's per attention block (4 pairs)

// Scratch (static device globals — no allocation)
__device__ __align__(16) float4 g_ca4[8 * 512];   // [k2][p] : h1 cols 4k2..4k2+3
__device__ float g_c[N_TOT * 16];                 // pooled-projection output (N,16)

// ---------------------------------------------------------------------------
__global__ void pre_ca(const float* __restrict__ cx, const float* __restrict__ Wa1) {
    int idx = blockIdx.x * blockDim.x + threadIdx.x;   // 4096 = 512p * 8k2
    int p = idx & 511, k2 = idx >> 9;
    float x0 = cx[p * 2 + 0], x1 = cx[p * 2 + 1];
    int j = 4 * k2;
    float4 v;
    v.x = x0 * Wa1[64 + j + 0] + x1 * Wa1[96 + j + 0];
    v.y = x0 * Wa1[64 + j + 1] + x1 * Wa1[96 + j + 1];
    v.z = x0 * Wa1[64 + j + 2] + x1 * Wa1[96 + j + 2];
    v.w = x0 * Wa1[64 + j + 3] + x1 * Wa1[96 + j + 3];
    g_ca4[k2 * 512 + p] = v;
}

// ---------------------------------------------------------------------------
// Attention: 4 pair-mainloops with NO block barriers inside the loop
// (softmax without max-shift; per-pair partials -> disjoint smem), then one
// deferred reduce + projection pass (3 barriers/block total).
__global__ __launch_bounds__(512) void attn_kernel(
    const float* __restrict__ r,
    const float* __restrict__ coeff_y,
    const float* __restrict__ Wa1,
    const float* __restrict__ Wa2,
    const float* __restrict__ Wa3,
    const float* __restrict__ Wp1, const float* __restrict__ bp1,
    const float* __restrict__ Wp2, const float* __restrict__ bp2)
{
    __shared__ __align__(16) float sWa2[1024];
    __shared__ __align__(16) float2 sQa[TN][16];
    __shared__ __align__(8)  float sWa3[32];
    __shared__ float sRedAll[TN / 2][16][10];   // per-pair per-warp partials
    __shared__ float sPoolAll[TN][5];
    __shared__ float sHpAll[TN][32];

    const int tid  = threadIdx.x;
    const int lane = tid & 31, warp = tid >> 5;
    const int n0 = blockIdx.x * TN;

    sWa2[tid]       = Wa2[tid];
    sWa2[tid + 512] = Wa2[tid + 512];
    if (tid < 32) sWa3[tid] = Wa3[tid];
    if (tid < TN * 16) {
        int t = tid >> 4, k = tid & 15;
        int n = n0 + t;
        float x0 = r[n * 4 + 0], x1 = r[n * 4 + 1];
        float q0 = x0 * Wa1[2 * k]     + x1 * Wa1[32 + 2 * k];
        float q1 = x0 * Wa1[2 * k + 1] + x1 * Wa1[32 + 2 * k + 1];
        sQa[t][k] = make_float2(q0, q1);
    }
    const float4 cy = reinterpret_cast<const float4*>(coeff_y)[tid];
    __syncthreads();                                            // B0

    float carry = 1.0f;   // always > 0; zero_of(carry) == +0.0

#pragma unroll 1
    for (int t2 = 0; t2 < TN / 2; ++t2) {
        const float4* qaA4 = reinterpret_cast<const float4*>(sQa[2 * t2]);
        const float4* qaB4 = reinterpret_cast<const float4*>(sQa[2 * t2 + 1]);

        // opaque dependence on previous pair's result: forbids ptxas from
        // pipelining accumulator chains across iterations (the spill mode).
        ULL seedv = dup2(zero_of(carry));

        ULL acc0[16], acc1[16];
        acc0[0] = seedv; acc1[0] = seedv;
#pragma unroll
        for (int q = 1; q < 16; ++q) { acc0[q] = 0ull; acc1[q] = 0ull; }

#pragma unroll
        for (int k2 = 0; k2 < 8; ++k2) {
            float4 ca  = g_ca4[k2 * 512 + tid];   // coalesced LDG.128, L1-hot
            float4 qaA = qaA4[k2];                // broadcast LDS.128
            float4 qaB = qaB4[k2];
            ULL aLo0 = dup2(fmaxf(qaA.x + ca.x, 0.f));
            ULL aHi0 = dup2(fmaxf(qaA.y + ca.y, 0.f));
            ULL aLo1 = dup2(fmaxf(qaA.z + ca.z, 0.f));
            ULL aHi1 = dup2(fmaxf(qaA.w + ca.w, 0.f));
            ULL bLo0 = dup2(fmaxf(qaB.x + ca.x, 0.f));
            ULL bHi0 = dup2(fmaxf(qaB.y + ca.y, 0.f));
            ULL bLo1 = dup2(fmaxf(qaB.z + ca.z, 0.f));
            ULL bHi1 = dup2(fmaxf(qaB.w + ca.w, 0.f));
            {   // Wa2 rows 4k2, 4k2+1
                const ulonglong2* r0 = reinterpret_cast<const ulonglong2*>(sWa2 + 128 * k2);
#pragma unroll
                for (int q = 0; q < 8; ++q) {
                    ulonglong2 w0 = r0[q];
                    ulonglong2 w1 = r0[q + 8];
                    acc0[2 * q]     = fma2(aLo0, w0.x, acc0[2 * q]);
                    acc0[2 * q + 1] = fma2(aLo0, w0.y, acc0[2 * q + 1]);
                    acc1[2 * q]     = fma2(bLo0, w0.x, acc1[2 * q]);
                    acc1[2 * q + 1] = fma2(bLo0, w0.y, acc1[2 * q + 1]);
                    acc0[2 * q]     = fma2(aHi0, w1.x, acc0[2 * q]);
                    acc0[2 * q + 1] = fma2(aHi0, w1.y, acc0[2 * q + 1]);
                    acc1[2 * q]     = fma2(bHi0, w1.x, acc1[2 * q]);
                    acc1[2 * q + 1] = fma2(bHi0, w1.y, acc1[2 * q + 1]);
                }
            }
            {   // Wa2 rows 4k2+2, 4k2+3
                const ulonglong2* r1 = reinterpret_cast<const ulonglong2*>(sWa2 + 128 * k2 + 64);
#pragma unroll
                for (int q = 0; q < 8; ++q) {
                    ulonglong2 w0 = r1[q];
                    ulonglong2 w1 = r1[q + 8];
                    acc0[2 * q]     = fma2(aLo1, w0.x, acc0[2 * q]);
                    acc0[2 * q + 1] = fma2(aLo1, w0.y, acc0[2 * q + 1]);
                    acc1[2 * q]     = fma2(bLo1, w0.x, acc1[2 * q]);
                    acc1[2 * q + 1] = fma2(bLo1, w0.y, acc1[2 * q + 1]);
                    acc0[2 * q]     = fma2(aHi1, w1.x, acc0[2 * q]);
                    acc0[2 * q + 1] = fma2(aHi1, w1.y, acc0[2 * q + 1]);
                    acc1[2 * q]     = fma2(bHi1, w1.x, acc1[2 * q]);
                    acc1[2 * q + 1] = fma2(bHi1, w1.y, acc1[2 * q + 1]);
                }
            }
        }

        float logitA = 0.f, logitB = 0.f;
#pragma unroll
        for (int q = 0; q < 16; ++q) {
            float2 w = reinterpret_cast<const float2*>(sWa3)[q];
            float2 a = unpk(acc0[q]);
            logitA += fmaxf(a.x, 0.f) * w.x + fmaxf(a.y, 0.f) * w.y;
            float2 b = unpk(acc1[q]);
            logitB += fmaxf(b.x, 0.f) * w.x + fmaxf(b.y, 0.f) * w.y;
        }

        // softmax WITHOUT max-shift (logits bounded far below exp overflow)
        float eA = __expf(logitA);
        float eB = __expf(logitB);
        float vA0 = eA, vA1 = eA * cy.x, vA2 = eA * cy.y, vA3 = eA * cy.z, vA4 = eA * cy.w;
        float vB0 = eB, vB1 = eB * cy.x, vB2 = eB * cy.y, vB3 = eB * cy.z, vB4 = eB * cy.w;
#pragma unroll
        for (int off = 16; off; off >>= 1) {
            vA0 += __shfl_xor_sync(0xffffffffu, vA0, off);
            vB0 += __shfl_xor_sync(0xffffffffu, vB0, off);
            vA1 += __shfl_xor_sync(0xffffffffu, vA1, off);
            vB1 += __shfl_xor_sync(0xffffffffu, vB1, off);
            vA2 += __shfl_xor_sync(0xffffffffu, vA2, off);
            vB2 += __shfl_xor_sync(0xffffffffu, vB2, off);
            vA3 += __shfl_xor_sync(0xffffffffu, vA3, off);
            vB3 += __shfl_xor_sync(0xffffffffu, vB3, off);
            vA4 += __shfl_xor_sync(0xffffffffu, vA4, off);
            vB4 += __shfl_xor_sync(0xffffffffu, vB4, off);
        }
        if (lane == 0) {
            sRedAll[t2][warp][0] = vA0; sRedAll[t2][warp][1] = vA1;
            sRedAll[t2][warp][2] = vA2; sRedAll[t2][warp][3] = vA3;
            sRedAll[t2][warp][4] = vA4;
            sRedAll[t2][warp][5] = vB0; sRedAll[t2][warp][6] = vB1;
            sRedAll[t2][warp][7] = vB2; sRedAll[t2][warp][8] = vB3;
            sRedAll[t2][warp][9] = vB4;
        }
        carry = vA0;   // > 0 always (sum of exps); feeds next pair's seed
    }
    __syncthreads();                                            // B1

    // ===== deferred reduce + projection for all 8 n's =====
    if (tid < TN * 5) {
        int t = tid / 5, j = tid % 5;
        float s = 0.f;
#pragma unroll
        for (int w = 0; w < 16; ++w) s += sRedAll[t >> 1][w][(t & 1) * 5 + j];
        sPoolAll[t][j] = s;
    }
    __syncthreads();                                            // B2
    if (tid < TN * 32) {
        int u = tid >> 5, j = tid & 31;
        float inv = 1.f / sPoolAll[u][0];
        float a0 = sPoolAll[u][1] * inv, a1 = sPoolAll[u][2] * inv;
        float a2 = sPoolAll[u][3] * inv, a3 = sPoolAll[u][4] * inv;
        float hp = bp1[j] + a0 * Wp1[j] + a1 * Wp1[32 + j]
                          + a2 * Wp1[64 + j] + a3 * Wp1[96 + j];
        sHpAll[u][j] = fmaxf(hp, 0.f);
    }
    __syncthreads();                                            // B3
    if (tid < TN * 16) {
        int u = tid >> 4, j = tid & 15;
        float cv = bp2[j];
#pragma unroll
        for (int k = 0; k < 32; ++k) cv += sHpAll[u][k] * Wp2[k * 16 + j];
        g_c[(n0 + u) * 16 + j] = cv;
    }
}

// ---------------------------------------------------------------------------
// Gating: block = 8 rows, 128 threads, grid 1024. (unchanged, proven)
__global__ __launch_bounds__(128) void gate_kernel(
    const float* __restrict__ r, const float* __restrict__ rp,
    const float* __restrict__ Wg1, const float* __restrict__ bg1,
    const float* __restrict__ Wg2, const float* __restrict__ bg2,
    const float* __restrict__ Wg3, const float* __restrict__ bg3,
    float* __restrict__ out)
{
    __shared__ float sX[8][25];
    __shared__ __align__(16) float sG1[256 * 8];   // [k][row]
    __shared__ float sPart[4][8];

    const int tid  = threadIdx.x;
    const int lane = tid & 31, warp = tid >> 5;   // warp 0..3
    const int n0 = blockIdx.x * 8;

    for (int idx = tid; idx < 8 * 24; idx += 128) {
        int row = idx / 24, j = idx % 24;
        int n = n0 + row;
        float v = (j < 4) ? r[n * 4 + j]
                : (j < 8) ? rp[n * 4 + (j - 4)]
                          : g_c[n * 16 + (j - 8)];
        sX[row][j] = v;
    }
    __syncthreads();

    // Stage A: warp w -> k in [64w, 64w+64); lane -> (row = lane&7, kq = lane>>3)
    {
        const int row = lane & 7, kq = lane >> 3;   // kq 0..3
        float x[24];
#pragma unroll
        for (int j = 0; j < 24; ++j) x[j] = sX[row][j];
        const int kbase = warp * 64 + kq;
#pragma unroll 4
        for (int kk = 0; kk < 16; ++kk) {
            int k = kbase + 4 * kk;
            float a = bg1[k];
#pragma unroll
            for (int j = 0; j < 24; ++j) a += x[j] * Wg1[j * 256 + k];
            sG1[k * 8 + row] = fmaxf(a, 0.f);
        }
    }
    __syncthreads();

    // Stage B: lane's two j columns
    const int jc0 = warp * 64 + lane;
    const int jc1 = jc0 + 32;

    ULL acc0[4], acc1[4];
    {
        ULL b0 = dup2(bg2[jc0]), b1 = dup2(bg2[jc1]);
#pragma unroll
        for (int i = 0; i < 4; ++i) { acc0[i] = b0; acc1[i] = b1; }
    }

    const float* w0 = Wg2 + jc0;
    const float* w1 = Wg2 + jc1;
    const ulonglong2* gRows = reinterpret_cast<const ulonglong2*>(sG1);

#pragma unroll 8
    for (int k = 0; k < 256; ++k) {
        ULL wa = dup2(w0[k * 256]);          // coalesced LDG.32
        ULL wb = dup2(w1[k * 256]);
        ulonglong2 g01 = gRows[k * 2 + 0];   // rows 0-3 (broadcast LDS.128)
        ulonglong2 g23 = gRows[k * 2 + 1];   // rows 4-7
        acc0[0] = fma2(g01.x, wa, acc0[0]);
        acc0[1] = fma2(g01.y, wa, acc0[1]);
        acc0[2] = fma2(g23.x, wa, acc0[2]);
        acc0[3] = fma2(g23.y, wa, acc0[3]);
        acc1[0] = fma2(g01.x, wb, acc1[0]);
        acc1[1] = fma2(g01.y, wb, acc1[1]);
        acc1[2] = fma2(g23.x, wb, acc1[2]);
        acc1[3] = fma2(g23.y, wb, acc1[3]);
    }

    // epilogue: relu, * Wg3, sum both j, reduce across lanes, then warps
    float w3a = Wg3[jc0], w3b = Wg3[jc1];
    float rv[8];
#pragma unroll
    for (int i = 0; i < 4; ++i) {
        float2 a = unpk(acc0[i]);
        float2 b = unpk(acc1[i]);
        rv[2 * i]     = fmaxf(a.x, 0.f) * w3a + fmaxf(b.x, 0.f) * w3b;
        rv[2 * i + 1] = fmaxf(a.y, 0.f) * w3a + fmaxf(b.y, 0.f) * w3b;
    }
#pragma unroll
    for (int off = 16; off; off >>= 1) {
#pragma unroll
        for (int i = 0; i < 8; ++i)
            rv[i] += __shfl_xor_sync(0xffffffffu, rv[i], off);
    }
    if (lane == 0) {
#pragma unroll
        for (int i = 0; i < 8; ++i) sPart[warp][i] = rv[i];
    }
    __syncthreads();

    if (tid < 8) {
        float s = bg3[0];
#pragma unroll
        for (int w = 0; w < 4; ++w) s += sPart[w][tid];
        out[n0 + tid] = __expf(s);
    }
}

// ---------------------------------------------------------------------------
extern "C" void kernel_launch(void* const* d_in, const int* in_sizes, int n_in,
                              void* d_out, int out_size) {
    (void)in_sizes; (void)n_in; (void)out_size;
    const float* r   = (const float*)d_in[0];
    const float* rp  = (const float*)d_in[1];
    const float* cx  = (const float*)d_in[2];
    const float* cy  = (const float*)d_in[3];
    const float* Wa1 = (const float*)d_in[4];
    const float* Wa2 = (const float*)d_in[5];
    const float* Wa3 = (const float*)d_in[6];
    const float* Wp1 = (const float*)d_in[7];
    const float* bp1 = (const float*)d_in[8];
    const float* Wp2 = (const float*)d_in[9];
    const float* bp2 = (const float*)d_in[10];
    const float* Wg1 = (const float*)d_in[11];
    const float* bg1 = (const float*)d_in[12];
    const float* Wg2 = (const float*)d_in[13];
    const float* bg2 = (const float*)d_in[14];
    const float* Wg3 = (const float*)d_in[15];
    const float* bg3 = (const float*)d_in[16];
    float* out = (float*)d_out;

    pre_ca<<<8, 512>>>(cx, Wa1);
    attn_kernel<<<N_TOT / TN, 512>>>(r, cy, Wa1, Wa2, Wa3, Wp1, bp1, Wp2, bp2);
    gate_kernel<<<N_TOT / 8, 128>>>(r, rp, Wg1, bg1, Wg2, bg2, Wg3, bg3, out);
}

// round 12
// speedup vs baseline: 15.5491x; 15.5491x over previous
#include <cuda_runtime.h>

typedef unsigned long long ULL;

__device__ __forceinline__ ULL fma2(ULL a, ULL b, ULL c) {
    ULL d;
    asm("fma.rn.f32x2 %0, %1, %2, %3;" : "=l"(d) : "l"(a), "l"(b), "l"(c));
    return d;
}
__device__ __forceinline__ ULL dup2(float x) {
    ULL d;
    asm("mov.b64 %0, {%1, %1};" : "=l"(d) : "f"(x));
    return d;
}
__device__ __forceinline__ float2 unpk(ULL v) {
    float2 r;
    asm("mov.b64 {%0, %1}, %2;" : "=f"(r.x), "=f"(r.y) : "l"(v));
    return r;
}

#define N_TOT 8192
#define TN 8          // n's per attention block

// Scratch (static device globals — no allocation)
__device__ __align__(16) float4 g_ca4[8 * 512];   // [k2][p] : h1 cols 4k2..4k2+3
__device__ float g_c[N_TOT * 16];                 // pooled-projection output (N,16)

// ---------------------------------------------------------------------------
__global__ void pre_ca(const float* __restrict__ cx, const float* __restrict__ Wa1) {
    int idx = blockIdx.x * blockDim.x + threadIdx.x;   // 4096 = 512p * 8k2
    int p = idx & 511, k2 = idx >> 9;
    float x0 = cx[p * 2 + 0], x1 = cx[p * 2 + 1];
    int j = 4 * k2;
    float4 v;
    v.x = x0 * Wa1[64 + j + 0] + x1 * Wa1[96 + j + 0];
    v.y = x0 * Wa1[64 + j + 1] + x1 * Wa1[96 + j + 1];
    v.z = x0 * Wa1[64 + j + 2] + x1 * Wa1[96 + j + 2];
    v.w = x0 * Wa1[64 + j + 3] + x1 * Wa1[96 + j + 3];
    g_ca4[k2 * 512 + p] = v;
}

// ---------------------------------------------------------------------------
// Attention: 256 threads (2 blocks/SM), thread owns p = tid and p + 256.
// Per-n mainloop + per-n epilogue with IN-LOOP barriers (proven spill fence).
__global__ __launch_bounds__(256, 2) void attn_kernel(
    const float* __restrict__ r,
    const float* __restrict__ coeff_y,
    const float* __restrict__ Wa1,
    const float* __restrict__ Wa2,
    const float* __restrict__ Wa3,
    const float* __restrict__ Wp1, const float* __restrict__ bp1,
    const float* __restrict__ Wp2, const float* __restrict__ bp2)
{
    __shared__ __align__(16) float sWa2[1024];
    __shared__ __align__(16) float2 sQa[TN][16];
    __shared__ __align__(8)  float sWa3[32];
    __shared__ float sMax[8];
    __shared__ float sRed[8][5];
    __shared__ float sPool[5];
    __shared__ float sHp[32];

    const int tid  = threadIdx.x;
    const int lane = tid & 31, warp = tid >> 5;   // warp 0..7
    const int n0 = blockIdx.x * TN;

#pragma unroll
    for (int i = 0; i < 4; ++i) sWa2[tid + 256 * i] = Wa2[tid + 256 * i];
    if (tid < 32) sWa3[tid] = Wa3[tid];
    if (tid < TN * 16) {
        int t = tid >> 4, k = tid & 15;
        int n = n0 + t;
        float x0 = r[n * 4 + 0], x1 = r[n * 4 + 1];
        float q0 = x0 * Wa1[2 * k]     + x1 * Wa1[32 + 2 * k];
        float q1 = x0 * Wa1[2 * k + 1] + x1 * Wa1[32 + 2 * k + 1];
        sQa[t][k] = make_float2(q0, q1);
    }
    const float4 cy0 = reinterpret_cast<const float4*>(coeff_y)[tid];
    const float4 cy1 = reinterpret_cast<const float4*>(coeff_y)[tid + 256];
    __syncthreads();

#pragma unroll 1
    for (int t = 0; t < TN; ++t) {
        const float4* qa4 = reinterpret_cast<const float4*>(sQa[t]);

        ULL acc0[16], acc1[16];
#pragma unroll
        for (int q = 0; q < 16; ++q) { acc0[q] = 0ull; acc1[q] = 0ull; }

#pragma unroll
        for (int k2 = 0; k2 < 8; ++k2) {
            float4 ca0 = g_ca4[k2 * 512 + tid];         // p = tid
            float4 ca1 = g_ca4[k2 * 512 + tid + 256];   // p = tid + 256
            float4 qa  = qa4[k2];                       // broadcast LDS.128
            ULL aLo0 = dup2(fmaxf(qa.x + ca0.x, 0.f));
            ULL aHi0 = dup2(fmaxf(qa.y + ca0.y, 0.f));
            ULL aLo1 = dup2(fmaxf(qa.z + ca0.z, 0.f));
            ULL aHi1 = dup2(fmaxf(qa.w + ca0.w, 0.f));
            ULL bLo0 = dup2(fmaxf(qa.x + ca1.x, 0.f));
            ULL bHi0 = dup2(fmaxf(qa.y + ca1.y, 0.f));
            ULL bLo1 = dup2(fmaxf(qa.z + ca1.z, 0.f));
            ULL bHi1 = dup2(fmaxf(qa.w + ca1.w, 0.f));
            {   // Wa2 rows 4k2, 4k2+1
                const ulonglong2* r0 = reinterpret_cast<const ulonglong2*>(sWa2 + 128 * k2);
#pragma unroll
                for (int q = 0; q < 8; ++q) {
                    ulonglong2 w0 = r0[q];
                    ulonglong2 w1 = r0[q + 8];
                    acc0[2 * q]     = fma2(aLo0, w0.x, acc0[2 * q]);
                    acc0[2 * q + 1] = fma2(aLo0, w0.y, acc0[2 * q + 1]);
                    acc1[2 * q]     = fma2(bLo0, w0.x, acc1[2 * q]);
                    acc1[2 * q + 1] = fma2(bLo0, w0.y, acc1[2 * q + 1]);
                    acc0[2 * q]     = fma2(aHi0, w1.x, acc0[2 * q]);
                    acc0[2 * q + 1] = fma2(aHi0, w1.y, acc0[2 * q + 1]);
                    acc1[2 * q]     = fma2(bHi0, w1.x, acc1[2 * q]);
                    acc1[2 * q + 1] = fma2(bHi0, w1.y, acc1[2 * q + 1]);
                }
            }
            {   // Wa2 rows 4k2+2, 4k2+3
                const ulonglong2* r1 = reinterpret_cast<const ulonglong2*>(sWa2 + 128 * k2 + 64);
#pragma unroll
                for (int q = 0; q < 8; ++q) {
                    ulonglong2 w0 = r1[q];
                    ulonglong2 w1 = r1[q + 8];
                    acc0[2 * q]     = fma2(aLo1, w0.x, acc0[2 * q]);
                    acc0[2 * q + 1] = fma2(aLo1, w0.y, acc0[2 * q + 1]);
                    acc1[2 * q]     = fma2(bLo1, w0.x, acc1[2 * q]);
                    acc1[2 * q + 1] = fma2(bLo1, w0.y, acc1[2 * q + 1]);
                    acc0[2 * q]     = fma2(aHi1, w1.x, acc0[2 * q]);
                    acc0[2 * q + 1] = fma2(aHi1, w1.y, acc0[2 * q + 1]);
                    acc1[2 * q]     = fma2(bHi1, w1.x, acc1[2 * q]);
                    acc1[2 * q + 1] = fma2(bHi1, w1.y, acc1[2 * q + 1]);
                }
            }
        }

        float logit0 = 0.f, logit1 = 0.f;
#pragma unroll
        for (int q = 0; q < 16; ++q) {
            float2 w = reinterpret_cast<const float2*>(sWa3)[q];
            float2 a = unpk(acc0[q]);
            logit0 += fmaxf(a.x, 0.f) * w.x + fmaxf(a.y, 0.f) * w.y;
            float2 b = unpk(acc1[q]);
            logit1 += fmaxf(b.x, 0.f) * w.x + fmaxf(b.y, 0.f) * w.y;
        }

        // ===== per-n epilogue (barriers IN-LOOP: the proven spill fence) =====
        float m = fmaxf(logit0, logit1);
#pragma unroll
        for (int off = 16; off; off >>= 1)
            m = fmaxf(m, __shfl_xor_sync(0xffffffffu, m, off));
        if (lane == 0) sMax[warp] = m;
        __syncthreads();                                        // B1
        float gm = sMax[0];
#pragma unroll
        for (int w = 1; w < 8; ++w) gm = fmaxf(gm, sMax[w]);

        float e0 = __expf(logit0 - gm);
        float e1 = __expf(logit1 - gm);
        float v0 = e0 + e1;
        float v1 = e0 * cy0.x + e1 * cy1.x;
        float v2 = e0 * cy0.y + e1 * cy1.y;
        float v3 = e0 * cy0.z + e1 * cy1.z;
        float v4 = e0 * cy0.w + e1 * cy1.w;
#pragma unroll
        for (int off = 16; off; off >>= 1) {
            v0 += __shfl_xor_sync(0xffffffffu, v0, off);
            v1 += __shfl_xor_sync(0xffffffffu, v1, off);
            v2 += __shfl_xor_sync(0xffffffffu, v2, off);
            v3 += __shfl_xor_sync(0xffffffffu, v3, off);
            v4 += __shfl_xor_sync(0xffffffffu, v4, off);
        }
        if (lane == 0) {
            sRed[warp][0] = v0; sRed[warp][1] = v1; sRed[warp][2] = v2;
            sRed[warp][3] = v3; sRed[warp][4] = v4;
        }
        __syncthreads();                                        // B2
        if (tid < 5) {
            float s = 0.f;
#pragma unroll
            for (int w = 0; w < 8; ++w) s += sRed[w][tid];
            sPool[tid] = s;
        }
        __syncthreads();                                        // B3
        if (tid < 32) {
            float inv = 1.f / sPool[0];
            float a0 = sPool[1] * inv, a1 = sPool[2] * inv;
            float a2 = sPool[3] * inv, a3 = sPool[4] * inv;
            float hp = bp1[tid] + a0 * Wp1[tid] + a1 * Wp1[32 + tid]
                                + a2 * Wp1[64 + tid] + a3 * Wp1[96 + tid];
            sHp[tid] = fmaxf(hp, 0.f);
        }
        __syncthreads();                                        // B4
        if (tid < 16) {
            float cv = bp2[tid];
#pragma unroll
            for (int k = 0; k < 32; ++k) cv += sHp[k] * Wp2[k * 16 + tid];
            g_c[(n0 + t) * 16 + tid] = cv;
        }
        // buffer reuse safety: sMax read before B2, rewritten after next B4+
        // mainloop (ordered by B2..B4 + B1'); sRed read after B2, rewritten
        // pre-B2' (ordered by B3,B4,B1'); sPool read after B3, rewritten
        // post-B2' (ordered); sHp read after B4, rewritten post-B3' (ordered).
    }
}

// ---------------------------------------------------------------------------
// Gating: block = 8 rows, 128 threads, grid 1024. (unchanged, proven)
__global__ __launch_bounds__(128) void gate_kernel(
    const float* __restrict__ r, const float* __restrict__ rp,
    const float* __restrict__ Wg1, const float* __restrict__ bg1,
    const float* __restrict__ Wg2, const float* __restrict__ bg2,
    const float* __restrict__ Wg3, const float* __restrict__ bg3,
    float* __restrict__ out)
{
    __shared__ float sX[8][25];
    __shared__ __align__(16) float sG1[256 * 8];   // [k][row]
    __shared__ float sPart[4][8];

    const int tid  = threadIdx.x;
    const int lane = tid & 31, warp = tid >> 5;   // warp 0..3
    const int n0 = blockIdx.x * 8;

    for (int idx = tid; idx < 8 * 24; idx += 128) {
        int row = idx / 24, j = idx % 24;
        int n = n0 + row;
        float v = (j < 4) ? r[n * 4 + j]
                : (j < 8) ? rp[n * 4 + (j - 4)]
                          : g_c[n * 16 + (j - 8)];
        sX[row][j] = v;
    }
    __syncthreads();

    // Stage A: warp w -> k in [64w, 64w+64); lane -> (row = lane&7, kq = lane>>3)
    {
        const int row = lane & 7, kq = lane >> 3;   // kq 0..3
        float x[24];
#pragma unroll
        for (int j = 0; j < 24; ++j) x[j] = sX[row][j];
        const int kbase = warp * 64 + kq;
#pragma unroll 4
        for (int kk = 0; kk < 16; ++kk) {
            int k = kbase + 4 * kk;
            float a = bg1[k];
#pragma unroll
            for (int j = 0; j < 24; ++j) a += x[j] * Wg1[j * 256 + k];
            sG1[k * 8 + row] = fmaxf(a, 0.f);
        }
    }
    __syncthreads();

    // Stage B: lane's two j columns
    const int jc0 = warp * 64 + lane;
    const int jc1 = jc0 + 32;

    ULL acc0[4], acc1[4];
    {
        ULL b0 = dup2(bg2[jc0]), b1 = dup2(bg2[jc1]);
#pragma unroll
        for (int i = 0; i < 4; ++i) { acc0[i] = b0; acc1[i] = b1; }
    }

    const float* w0 = Wg2 + jc0;
    const float* w1 = Wg2 + jc1;
    const ulonglong2* gRows = reinterpret_cast<const ulonglong2*>(sG1);

#pragma unroll 8
    for (int k = 0; k < 256; ++k) {
        ULL wa = dup2(w0[k * 256]);          // coalesced LDG.32
        ULL wb = dup2(w1[k * 256]);
        ulonglong2 g01 = gRows[k * 2 + 0];   // rows 0-3 (broadcast LDS.128)
        ulonglong2 g23 = gRows[k * 2 + 1];   // rows 4-7
        acc0[0] = fma2(g01.x, wa, acc0[0]);
        acc0[1] = fma2(g01.y, wa, acc0[1]);
        acc0[2] = fma2(g23.x, wa, acc0[2]);
        acc0[3] = fma2(g23.y, wa, acc0[3]);
        acc1[0] = fma2(g01.x, wb, acc1[0]);
        acc1[1] = fma2(g01.y, wb, acc1[1]);
        acc1[2] = fma2(g23.x, wb, acc1[2]);
        acc1[3] = fma2(g23.y, wb, acc1[3]);
    }

    // epilogue: relu, * Wg3, sum both j, reduce across lanes, then warps
    float w3a = Wg3[jc0], w3b = Wg3[jc1];
    float rv[8];
#pragma unroll
    for (int i = 0; i < 4; ++i) {
        float2 a = unpk(acc0[i]);
        float2 b = unpk(acc1[i]);
        rv[2 * i]     = fmaxf(a.x, 0.f) * w3a + fmaxf(b.x, 0.f) * w3b;
        rv[2 * i + 1] = fmaxf(a.y, 0.f) * w3a + fmaxf(b.y, 0.f) * w3b;
    }
#pragma unroll
    for (int off = 16; off; off >>= 1) {
#pragma unroll
        for (int i = 0; i < 8; ++i)
            rv[i] += __shfl_xor_sync(0xffffffffu, rv[i], off);
    }
    if (lane == 0) {
#pragma unroll
        for (int i = 0; i < 8; ++i) sPart[warp][i] = rv[i];
    }
    __syncthreads();

    if (tid < 8) {
        float s = bg3[0];
#pragma unroll
        for (int w = 0; w < 4; ++w) s += sPart[w][tid];
        out[n0 + tid] = __expf(s);
    }
}

// ---------------------------------------------------------------------------
extern "C" void kernel_launch(void* const* d_in, const int* in_sizes, int n_in,
                              void* d_out, int out_size) {
    (void)in_sizes; (void)n_in; (void)out_size;
    const float* r   = (const float*)d_in[0];
    const float* rp  = (const float*)d_in[1];
    const float* cx  = (const float*)d_in[2];
    const float* cy  = (const float*)d_in[3];
    const float* Wa1 = (const float*)d_in[4];
    const float* Wa2 = (const float*)d_in[5];
    const float* Wa3 = (const float*)d_in[6];
    const float* Wp1 = (const float*)d_in[7];
    const float* bp1 = (const float*)d_in[8];
    const float* Wp2 = (const float*)d_in[9];
    const float* bp2 = (const float*)d_in[10];
    const float* Wg1 = (const float*)d_in[11];
    const float* bg1 = (const float*)d_in[12];
    const float* Wg2 = (const float*)d_in[13];
    const float* bg2 = (const float*)d_in[14];
    const float* Wg3 = (const float*)d_in[15];
    const float* bg3 = (const float*)d_in[16];
    float* out = (float*)d_out;

    pre_ca<<<8, 512>>>(cx, Wa1);
    attn_kernel<<<N_TOT / TN, 256>>>(r, cy, Wa1, Wa2, Wa3, Wp1, bp1, Wp2, bp2);
    gate_kernel<<<N_TOT / 8, 128>>>(r, rp, Wg1, bg1, Wg2, bg2, Wg3, bg3, out);
}